// round 2
// baseline (speedup 1.0000x reference)
#include <cuda_runtime.h>
#include <math.h>

#define B_SAMP 8192
#define P_RAW  4849
#define P_PAD  4852          // pad rows to multiple of 4 floats for aligned stores
#define HWID   96

// 159 MB scratch for per-sample flat params (device global = sanctioned scratch)
__device__ float g_p[(size_t)B_SAMP * P_PAD];

// ---------------------------------------------------------------------------
// Kernel 1: fused hypernet + GEMM
//   h[s,k]  = relu(x[s]*hw1[k,0] + c[s]*hw1[k,1] + hb1[k])   (computed in tile load)
//   p[s,i]  = sum_k h[s,k]*hw2[i,k] + hb2[i]
// ---------------------------------------------------------------------------
#define BM 128
#define BN 128
#define LDSS 132                     // padded smem row stride (floats)
#define GEMM_THREADS 256
#define GEMM_SMEM (2 * 96 * LDSS * 4)

__global__ __launch_bounds__(GEMM_THREADS)
void gemm_kernel(const float* __restrict__ x, const float* __restrict__ c,
                 const float* __restrict__ hw1, const float* __restrict__ hb1,
                 const float* __restrict__ hw2, const float* __restrict__ hb2)
{
    extern __shared__ float sm[];
    float* As = sm;                    // [96][LDSS] : h, transposed (k-major outer)
    float* Bs = sm + 96 * LDSS;        // [96][LDSS] : hw2 tile, transposed

    const int t  = threadIdx.x;
    const int s0 = blockIdx.y * BM;
    const int p0 = blockIdx.x * BN;

    // Load A tile: compute hypernet hidden layer on the fly
    for (int i = t; i < BM * 96; i += GEMM_THREADS) {
        int sl = i / 96, k = i - sl * 96;
        int s = s0 + sl;
        float h = fmaf(x[s], hw1[2 * k], fmaf(c[s], hw1[2 * k + 1], hb1[k]));
        As[k * LDSS + sl] = fmaxf(h, 0.f);
    }
    // Load B tile (guard last param tile)
    for (int i = t; i < BN * 96; i += GEMM_THREADS) {
        int pl = i / 96, k = i - pl * 96;
        int pp = p0 + pl;
        Bs[k * LDSS + pl] = (pp < P_RAW) ? hw2[pp * 96 + k] : 0.f;
    }
    __syncthreads();

    const int tx = t & 15, ty = t >> 4;
    float acc[8][8];
#pragma unroll
    for (int i = 0; i < 8; i++)
#pragma unroll
        for (int j = 0; j < 8; j++) acc[i][j] = 0.f;

    const float* ap = As + ty * 8;
    const float* bp = Bs + tx * 8;
#pragma unroll 2
    for (int k = 0; k < 96; k++) {
        float4 a0 = *(const float4*)(ap + k * LDSS);
        float4 a1 = *(const float4*)(ap + k * LDSS + 4);
        float4 b0 = *(const float4*)(bp + k * LDSS);
        float4 b1 = *(const float4*)(bp + k * LDSS + 4);
        float a[8] = {a0.x, a0.y, a0.z, a0.w, a1.x, a1.y, a1.z, a1.w};
        float b[8] = {b0.x, b0.y, b0.z, b0.w, b1.x, b1.y, b1.z, b1.w};
#pragma unroll
        for (int i = 0; i < 8; i++)
#pragma unroll
            for (int j = 0; j < 8; j++)
                acc[i][j] = fmaf(a[i], b[j], acc[i][j]);
    }

    // Epilogue: add bias, store
    float bias[8];
#pragma unroll
    for (int j = 0; j < 8; j++) {
        int pj = p0 + tx * 8 + j;
        bias[j] = (pj < P_RAW) ? hb2[pj] : 0.f;
    }
    bool full = (p0 + BN) <= P_RAW;
#pragma unroll
    for (int i = 0; i < 8; i++) {
        int s = s0 + ty * 8 + i;
        float* orow = g_p + (size_t)s * P_PAD + p0 + tx * 8;
        if (full) {
            float4 v0 = {acc[i][0] + bias[0], acc[i][1] + bias[1],
                         acc[i][2] + bias[2], acc[i][3] + bias[3]};
            float4 v1 = {acc[i][4] + bias[4], acc[i][5] + bias[5],
                         acc[i][6] + bias[6], acc[i][7] + bias[7]};
            *(float4*)orow = v0;
            *(float4*)(orow + 4) = v1;
        } else {
#pragma unroll
            for (int j = 0; j < 8; j++) {
                int pj = p0 + tx * 8 + j;
                if (pj < P_RAW) orow[j] = acc[i][j] + bias[j];
            }
        }
    }
}

// ---------------------------------------------------------------------------
// Kernel 2: per-sample Adam loop. One warp per sample, params in SMEM.
// g = f'(y): fused value+tangent pass through the 48-wide swish MLP.
// ---------------------------------------------------------------------------
#define SMEM_PER 4944                  // floats per sample in smem
#define ADAM_SMEM (4 * SMEM_PER * 4)   // 4 warps (samples) per CTA

__device__ __forceinline__ float sigf(float z) {
    return __fdividef(1.f, 1.f + __expf(-z));
}

__global__ __launch_bounds__(128)
void adam_kernel(float* __restrict__ out)
{
    extern __shared__ float sm[];
    const int lane = threadIdx.x & 31;
    const int wrp  = threadIdx.x >> 5;
    const int s    = blockIdx.x * 4 + wrp;

    float* S   = sm + wrp * SMEM_PER;
    float* W1T = S;             // [48k][48r] transposed: conflict-free row reads
    float* W2T = S + 2304;
    float* w0s = S + 4608;
    float* b0s = S + 4656;
    float* b1s = S + 4704;
    float* b2s = S + 4752;
    float* w3s = S + 4800;
    float* HD  = S + 4848;      // interleaved h/dh, 96 floats

    // Cooperative load of flat params; transpose w1/w2 on the fly
    const float* gp = g_p + (size_t)s * P_PAD;
    for (int i = lane; i < 4848; i += 32) {
        float v = gp[i];
        if (i < 48)            w0s[i] = v;
        else if (i < 96)       b0s[i - 48] = v;
        else if (i < 2400)   { int j = i - 96;   int r = j / 48, k = j - r * 48; W1T[k * 48 + r] = v; }
        else if (i < 2448)     b1s[i - 2400] = v;
        else if (i < 4752)   { int j = i - 2448; int r = j / 48, k = j - r * 48; W2T[k * 48 + r] = v; }
        else if (i < 4800)     b2s[i - 4752] = v;
        else                   w3s[i - 4800] = v;
    }
    __syncwarp();

    // Row ownership: every lane owns row `lane`; lanes 0..15 also own row lane+32
    const bool two = lane < 16;
    const int  rb  = lane + 32;
    const float w0a = w0s[lane],           b0a = b0s[lane];
    const float w0b = two ? w0s[rb] : 0.f, b0b = two ? b0s[rb] : 0.f;
    const float w3a = w3s[lane],           w3b = two ? w3s[rb] : 0.f;
    const float b1a = b1s[lane],           b1b = two ? b1s[rb] : 0.f;
    const float b2a = b2s[lane],           b2b = two ? b2s[rb] : 0.f;

    float y = 0.f, m = 0.f, v = 0.f;
    float c1 = 1.f, c2 = 1.f;

#pragma unroll 1
    for (int step = 0; step < 20; step++) {
        // ----- layer 0: z0 = w0*y + b0 ; tangent dz0/dy = w0 -----
        {
            float z = fmaf(w0a, y, b0a);
            float sg = sigf(z);
            HD[2 * lane]     = z * sg;                               // h1
            HD[2 * lane + 1] = sg * fmaf(z, 1.f - sg, 1.f) * w0a;    // swish'(z0)*w0
            if (two) {
                float zb = fmaf(w0b, y, b0b);
                float sb = sigf(zb);
                HD[2 * rb]     = zb * sb;
                HD[2 * rb + 1] = sb * fmaf(zb, 1.f - sb, 1.f) * w0b;
            }
        }
        __syncwarp();

        // ----- layer 1: z1 = w1 h1 + b1 ; t1 = w1 th1 -----
        float za = b1a, ta = 0.f, zb = b1b, tb = 0.f;
#pragma unroll
        for (int k = 0; k < 48; k++) {
            float2 hd = *(const float2*)(HD + 2 * k);   // broadcast
            float wa = W1T[k * 48 + lane];
            za = fmaf(wa, hd.x, za); ta = fmaf(wa, hd.y, ta);
            if (two) {
                float wb = W1T[k * 48 + rb];
                zb = fmaf(wb, hd.x, zb); tb = fmaf(wb, hd.y, tb);
            }
        }
        __syncwarp();   // all lanes done reading HD before overwrite
        {
            float sg = sigf(za);
            HD[2 * lane]     = za * sg;
            HD[2 * lane + 1] = sg * fmaf(za, 1.f - sg, 1.f) * ta;
            if (two) {
                float sb = sigf(zb);
                HD[2 * rb]     = zb * sb;
                HD[2 * rb + 1] = sb * fmaf(zb, 1.f - sb, 1.f) * tb;
            }
        }
        __syncwarp();

        // ----- layer 2 + linear output (only tangent needed for grad) -----
        za = b2a; ta = 0.f; zb = b2b; tb = 0.f;
#pragma unroll
        for (int k = 0; k < 48; k++) {
            float2 hd = *(const float2*)(HD + 2 * k);
            float wa = W2T[k * 48 + lane];
            za = fmaf(wa, hd.x, za); ta = fmaf(wa, hd.y, ta);
            if (two) {
                float wb = W2T[k * 48 + rb];
                zb = fmaf(wb, hd.x, zb); tb = fmaf(wb, hd.y, tb);
            }
        }
        float sg = sigf(za);
        float g = w3a * (sg * fmaf(za, 1.f - sg, 1.f) * ta);
        if (two) {
            float sb = sigf(zb);
            g += w3b * (sb * fmaf(zb, 1.f - sb, 1.f) * tb);
        }
#pragma unroll
        for (int o = 16; o; o >>= 1) g += __shfl_xor_sync(0xffffffffu, g, o);

        // ----- Adam update (replicated in all lanes) -----
        c1 *= 0.9f; c2 *= 0.999f;
        m = fmaf(0.9f, m, 0.1f * g);
        v = fmaf(0.999f, v, 0.001f * g * g);
        float mh = m / (1.f - c1);
        float vh = v / (1.f - c2);
        y -= 0.1f * mh / (sqrtf(vh) + 1e-8f);
        __syncwarp();
    }

    if (lane == 0) out[s] = y;
}

// ---------------------------------------------------------------------------
extern "C" void kernel_launch(void* const* d_in, const int* in_sizes, int n_in,
                              void* d_out, int out_size)
{
    const float* x   = (const float*)d_in[0];
    const float* c   = (const float*)d_in[1];
    const float* hw1 = (const float*)d_in[2];
    const float* hb1 = (const float*)d_in[3];
    const float* hw2 = (const float*)d_in[4];
    const float* hb2 = (const float*)d_in[5];
    float* out = (float*)d_out;

    cudaFuncSetAttribute(gemm_kernel, cudaFuncAttributeMaxDynamicSharedMemorySize, GEMM_SMEM);
    cudaFuncSetAttribute(adam_kernel, cudaFuncAttributeMaxDynamicSharedMemorySize, ADAM_SMEM);

    dim3 ggrid((P_RAW + BN - 1) / BN, B_SAMP / BM);   // 38 x 64
    gemm_kernel<<<ggrid, GEMM_THREADS, GEMM_SMEM>>>(x, c, hw1, hb1, hw2, hb2);
    adam_kernel<<<B_SAMP / 4, 128, ADAM_SMEM>>>(out);
}

// round 3
// speedup vs baseline: 1.4489x; 1.4489x over previous
#include <cuda_runtime.h>
#include <math.h>

#define B_SAMP 8192
#define P_RAW  4849
#define P_PAD  4852
#define HWID   96

// 159 MB scratch for per-sample flat params (device global = sanctioned scratch)
__device__ float g_p[(size_t)B_SAMP * P_PAD];

// ---------------------------------------------------------------------------
// Kernel 1: fused hypernet + GEMM  (unchanged from R2 — near fp32 FMA roofline)
// ---------------------------------------------------------------------------
#define BM 128
#define BN 128
#define LDSS 132
#define GEMM_THREADS 256
#define GEMM_SMEM (2 * 96 * LDSS * 4)

__global__ __launch_bounds__(GEMM_THREADS)
void gemm_kernel(const float* __restrict__ x, const float* __restrict__ c,
                 const float* __restrict__ hw1, const float* __restrict__ hb1,
                 const float* __restrict__ hw2, const float* __restrict__ hb2)
{
    extern __shared__ float sm[];
    float* As = sm;
    float* Bs = sm + 96 * LDSS;

    const int t  = threadIdx.x;
    const int s0 = blockIdx.y * BM;
    const int p0 = blockIdx.x * BN;

    for (int i = t; i < BM * 96; i += GEMM_THREADS) {
        int sl = i / 96, k = i - sl * 96;
        int s = s0 + sl;
        float h = fmaf(x[s], hw1[2 * k], fmaf(c[s], hw1[2 * k + 1], hb1[k]));
        As[k * LDSS + sl] = fmaxf(h, 0.f);
    }
    for (int i = t; i < BN * 96; i += GEMM_THREADS) {
        int pl = i / 96, k = i - pl * 96;
        int pp = p0 + pl;
        Bs[k * LDSS + pl] = (pp < P_RAW) ? hw2[pp * 96 + k] : 0.f;
    }
    __syncthreads();

    const int tx = t & 15, ty = t >> 4;
    float acc[8][8];
#pragma unroll
    for (int i = 0; i < 8; i++)
#pragma unroll
        for (int j = 0; j < 8; j++) acc[i][j] = 0.f;

    const float* ap = As + ty * 8;
    const float* bp = Bs + tx * 8;
#pragma unroll 2
    for (int k = 0; k < 96; k++) {
        float4 a0 = *(const float4*)(ap + k * LDSS);
        float4 a1 = *(const float4*)(ap + k * LDSS + 4);
        float4 b0 = *(const float4*)(bp + k * LDSS);
        float4 b1 = *(const float4*)(bp + k * LDSS + 4);
        float a[8] = {a0.x, a0.y, a0.z, a0.w, a1.x, a1.y, a1.z, a1.w};
        float b[8] = {b0.x, b0.y, b0.z, b0.w, b1.x, b1.y, b1.z, b1.w};
#pragma unroll
        for (int i = 0; i < 8; i++)
#pragma unroll
            for (int j = 0; j < 8; j++)
                acc[i][j] = fmaf(a[i], b[j], acc[i][j]);
    }

    float bias[8];
#pragma unroll
    for (int j = 0; j < 8; j++) {
        int pj = p0 + tx * 8 + j;
        bias[j] = (pj < P_RAW) ? hb2[pj] : 0.f;
    }
    bool full = (p0 + BN) <= P_RAW;
#pragma unroll
    for (int i = 0; i < 8; i++) {
        int s = s0 + ty * 8 + i;
        float* orow = g_p + (size_t)s * P_PAD + p0 + tx * 8;
        if (full) {
            float4 v0 = {acc[i][0] + bias[0], acc[i][1] + bias[1],
                         acc[i][2] + bias[2], acc[i][3] + bias[3]};
            float4 v1 = {acc[i][4] + bias[4], acc[i][5] + bias[5],
                         acc[i][6] + bias[6], acc[i][7] + bias[7]};
            *(float4*)orow = v0;
            *(float4*)(orow + 4) = v1;
        } else {
#pragma unroll
            for (int j = 0; j < 8; j++) {
                int pj = p0 + tx * 8 + j;
                if (pj < P_RAW) orow[j] = acc[i][j] + bias[j];
            }
        }
    }
}

// ---------------------------------------------------------------------------
// Kernel 2: per-sample Adam. One warp per sample. W1/W2 REGISTER-RESIDENT.
// Only the 96-float h/dh broadcast vector lives in SMEM.
// ---------------------------------------------------------------------------
__device__ __forceinline__ float sigf(float z) {
    return __fdividef(1.f, 1.f + __expf(-z));
}

__global__ __launch_bounds__(128, 2)
void adam_kernel(float* __restrict__ out)
{
    __shared__ float HD_all[4][100];   // interleaved h/dh per warp, 96 used
    const int lane = threadIdx.x & 31;
    const int wrp  = threadIdx.x >> 5;
    const int s    = blockIdx.x * 4 + wrp;
    float* HD = HD_all[wrp];

    const float* gp = g_p + (size_t)s * P_PAD;

    // Row ownership: lane owns row `lane`; lanes 0..15 also own row lane+32.
    const bool two = lane < 16;
    const int  ra  = lane;
    const int  rb  = two ? lane + 32 : lane;   // clamped (in-bounds); results unused

    // Register-resident weight rows (contiguous in g_p: w1[r*48+k] at 96, w2 at 2448)
    float w1a[48], w1b[48], w2a[48], w2b[48];
    {
        const float4* p1a = (const float4*)(gp + 96   + ra * 48);
        const float4* p1b = (const float4*)(gp + 96   + rb * 48);
        const float4* p2a = (const float4*)(gp + 2448 + ra * 48);
        const float4* p2b = (const float4*)(gp + 2448 + rb * 48);
#pragma unroll
        for (int q = 0; q < 12; q++) {
            ((float4*)w1a)[q] = p1a[q];
            ((float4*)w1b)[q] = p1b[q];
            ((float4*)w2a)[q] = p2a[q];
            ((float4*)w2b)[q] = p2b[q];
        }
    }
    const float w0a = gp[ra],        b0a = gp[48 + ra];
    const float w0b = gp[rb],        b0b = gp[48 + rb];
    const float b1a = gp[2400 + ra], b1b = gp[2400 + rb];
    const float b2a = gp[4752 + ra], b2b = gp[4752 + rb];
    const float w3a = gp[4800 + ra];
    const float w3b = two ? gp[4800 + rb] : 0.f;

    float y = 0.f, m = 0.f, v = 0.f;
    float c1 = 1.f, c2 = 1.f;

#pragma unroll 1
    for (int step = 0; step < 20; step++) {
        // ----- layer 0 -----
        {
            float z  = fmaf(w0a, y, b0a);
            float sg = sigf(z);
            float zb = fmaf(w0b, y, b0b);
            float sb = sigf(zb);
            *(float2*)(HD + 2 * ra) = make_float2(z * sg,
                                                  sg * fmaf(z, 1.f - sg, 1.f) * w0a);
            if (two)
                *(float2*)(HD + 2 * (lane + 32)) = make_float2(zb * sb,
                                                  sb * fmaf(zb, 1.f - sb, 1.f) * w0b);
        }
        __syncwarp();

        // ----- layer 1: value + tangent matvec, all-register weights -----
        float za = b1a, ta = 0.f, zb = b1b, tb = 0.f;
#pragma unroll
        for (int k = 0; k < 48; k++) {
            float2 hd = *(const float2*)(HD + 2 * k);
            za = fmaf(w1a[k], hd.x, za); ta = fmaf(w1a[k], hd.y, ta);
            zb = fmaf(w1b[k], hd.x, zb); tb = fmaf(w1b[k], hd.y, tb);
        }
        __syncwarp();
        {
            float sg = sigf(za);
            *(float2*)(HD + 2 * ra) = make_float2(za * sg,
                                                  sg * fmaf(za, 1.f - sg, 1.f) * ta);
            float sb = sigf(zb);
            if (two)
                *(float2*)(HD + 2 * (lane + 32)) = make_float2(zb * sb,
                                                  sb * fmaf(zb, 1.f - sb, 1.f) * tb);
        }
        __syncwarp();

        // ----- layer 2 + output (tangent only needed for grad) -----
        za = b2a; ta = 0.f; zb = b2b; tb = 0.f;
#pragma unroll
        for (int k = 0; k < 48; k++) {
            float2 hd = *(const float2*)(HD + 2 * k);
            za = fmaf(w2a[k], hd.x, za); ta = fmaf(w2a[k], hd.y, ta);
            zb = fmaf(w2b[k], hd.x, zb); tb = fmaf(w2b[k], hd.y, tb);
        }
        float sg = sigf(za);
        float g  = w3a * (sg * fmaf(za, 1.f - sg, 1.f) * ta);
        {
            float sb = sigf(zb);
            float gb = w3b * (sb * fmaf(zb, 1.f - sb, 1.f) * tb);
            if (two) g += gb;
        }
#pragma unroll
        for (int o = 16; o; o >>= 1) g += __shfl_xor_sync(0xffffffffu, g, o);

        // ----- Adam update (replicated across lanes) -----
        c1 *= 0.9f; c2 *= 0.999f;
        m = fmaf(0.9f, m, 0.1f * g);
        v = fmaf(0.999f, v, 0.001f * g * g);
        float mh = m / (1.f - c1);
        float vh = v / (1.f - c2);
        y -= 0.1f * mh / (sqrtf(vh) + 1e-8f);
        __syncwarp();
    }

    if (lane == 0) out[s] = y;
}

// ---------------------------------------------------------------------------
extern "C" void kernel_launch(void* const* d_in, const int* in_sizes, int n_in,
                              void* d_out, int out_size)
{
    const float* x   = (const float*)d_in[0];
    const float* c   = (const float*)d_in[1];
    const float* hw1 = (const float*)d_in[2];
    const float* hb1 = (const float*)d_in[3];
    const float* hw2 = (const float*)d_in[4];
    const float* hb2 = (const float*)d_in[5];
    float* out = (float*)d_out;

    cudaFuncSetAttribute(gemm_kernel, cudaFuncAttributeMaxDynamicSharedMemorySize, GEMM_SMEM);

    dim3 ggrid((P_RAW + BN - 1) / BN, B_SAMP / BM);   // 38 x 64
    gemm_kernel<<<ggrid, GEMM_THREADS, GEMM_SMEM>>>(x, c, hw1, hb1, hw2, hb2);
    adam_kernel<<<B_SAMP / 4, 128>>>(out);
}

// round 4
// speedup vs baseline: 2.1119x; 1.4576x over previous
#include <cuda_runtime.h>
#include <math.h>

#define B_SAMP 8192
#define P_RAW  4849
#define P_PAD  4852
#define HWID   96

typedef unsigned long long ull;

__device__ float g_p[(size_t)B_SAMP * P_PAD];

// ---- packed fp32x2 helpers (sm_103a FFMA2 via PTX) ----
#define FFMA2(d, a, b, c) \
    asm("fma.rn.f32x2 %0, %1, %2, %3;" : "=l"(d) : "l"(a), "l"(b), "l"(c))

__device__ __forceinline__ ull pack2(float lo, float hi) {
    ull r; asm("mov.b64 %0, {%1, %2};" : "=l"(r) : "f"(lo), "f"(hi)); return r;
}
__device__ __forceinline__ ull dup2(float v) {
    ull r; asm("mov.b64 %0, {%1, %1};" : "=l"(r) : "f"(v)); return r;
}
__device__ __forceinline__ void unpack2(ull v, float& lo, float& hi) {
    asm("mov.b64 {%0, %1}, %2;" : "=f"(lo), "=f"(hi) : "l"(v));
}

// ---------------------------------------------------------------------------
// Kernel 1: fused hypernet + GEMM, FFMA2 inner loop
// ---------------------------------------------------------------------------
#define BM 128
#define BN 128
#define LDSS 132
#define GEMM_THREADS 256
#define GEMM_SMEM (2 * 96 * LDSS * 4)

__global__ __launch_bounds__(GEMM_THREADS)
void gemm_kernel(const float* __restrict__ x, const float* __restrict__ c,
                 const float* __restrict__ hw1, const float* __restrict__ hb1,
                 const float* __restrict__ hw2, const float* __restrict__ hb2)
{
    extern __shared__ float sm[];
    float* As = sm;
    float* Bs = sm + 96 * LDSS;

    const int t  = threadIdx.x;
    const int s0 = blockIdx.y * BM;
    const int p0 = blockIdx.x * BN;

    for (int i = t; i < BM * 96; i += GEMM_THREADS) {
        int sl = i / 96, k = i - sl * 96;
        int s = s0 + sl;
        float h = fmaf(x[s], hw1[2 * k], fmaf(c[s], hw1[2 * k + 1], hb1[k]));
        As[k * LDSS + sl] = fmaxf(h, 0.f);
    }
    for (int i = t; i < BN * 96; i += GEMM_THREADS) {
        int pl = i / 96, k = i - pl * 96;
        int pp = p0 + pl;
        Bs[k * LDSS + pl] = (pp < P_RAW) ? hw2[pp * 96 + k] : 0.f;
    }
    __syncthreads();

    const int tx = t & 15, ty = t >> 4;
    // acc pairs: accp[i][jp] holds (acc[i][2jp], acc[i][2jp+1])
    ull accp[8][4];
#pragma unroll
    for (int i = 0; i < 8; i++)
#pragma unroll
        for (int jp = 0; jp < 4; jp++) accp[i][jp] = 0ull;

    const float* ap = As + ty * 8;
    const float* bp = Bs + tx * 8;
#pragma unroll 2
    for (int k = 0; k < 96; k++) {
        float4 a0 = *(const float4*)(ap + k * LDSS);
        float4 a1 = *(const float4*)(ap + k * LDSS + 4);
        ulonglong2 bq0 = *(const ulonglong2*)(bp + k * LDSS);      // (b0,b1),(b2,b3)
        ulonglong2 bq1 = *(const ulonglong2*)(bp + k * LDSS + 4);  // (b4,b5),(b6,b7)
        ull bq[4] = {bq0.x, bq0.y, bq1.x, bq1.y};
        ull ad[8] = {dup2(a0.x), dup2(a0.y), dup2(a0.z), dup2(a0.w),
                     dup2(a1.x), dup2(a1.y), dup2(a1.z), dup2(a1.w)};
#pragma unroll
        for (int i = 0; i < 8; i++)
#pragma unroll
            for (int jp = 0; jp < 4; jp++)
                FFMA2(accp[i][jp], ad[i], bq[jp], accp[i][jp]);
    }

    float bias[8];
#pragma unroll
    for (int j = 0; j < 8; j++) {
        int pj = p0 + tx * 8 + j;
        bias[j] = (pj < P_RAW) ? hb2[pj] : 0.f;
    }
    bool full = (p0 + BN) <= P_RAW;
#pragma unroll
    for (int i = 0; i < 8; i++) {
        int s = s0 + ty * 8 + i;
        float* orow = g_p + (size_t)s * P_PAD + p0 + tx * 8;
        float a[8];
#pragma unroll
        for (int jp = 0; jp < 4; jp++) unpack2(accp[i][jp], a[2 * jp], a[2 * jp + 1]);
        if (full) {
            float4 v0 = {a[0] + bias[0], a[1] + bias[1], a[2] + bias[2], a[3] + bias[3]};
            float4 v1 = {a[4] + bias[4], a[5] + bias[5], a[6] + bias[6], a[7] + bias[7]};
            *(float4*)orow = v0;
            *(float4*)(orow + 4) = v1;
        } else {
#pragma unroll
            for (int j = 0; j < 8; j++) {
                int pj = p0 + tx * 8 + j;
                if (pj < P_RAW) orow[j] = a[j] + bias[j];
            }
        }
    }
}

// ---------------------------------------------------------------------------
// Kernel 2: per-sample Adam. Packed FFMA2: accz=(row_a,row_b), acct likewise.
// SMEM holds (h,h,dh,dh) quads -> 1 LDS.128 + 2 FFMA2 per k.
// ---------------------------------------------------------------------------
__device__ __forceinline__ float sigf(float z) {
    return __fdividef(1.f, 1.f + __expf(-z));
}

__global__ __launch_bounds__(128, 2)
void adam_kernel(float* __restrict__ out)
{
    __shared__ __align__(16) float4 HD4_all[4][48];
    const int lane = threadIdx.x & 31;
    const int wrp  = threadIdx.x >> 5;
    const int s    = blockIdx.x * 4 + wrp;
    float4* HD4 = HD4_all[wrp];

    const float* gp = g_p + (size_t)s * P_PAD;

    const bool two = lane < 16;
    const int  ra  = lane;
    const int  rb  = two ? lane + 32 : lane;   // clamped; b-results unused when !two

    // Weight pairs: w1p[k] = (w1[ra][k], w1[rb][k]); same for w2p.  192 regs.
    ull w1p[48], w2p[48];
#pragma unroll
    for (int q = 0; q < 12; q++) {
        float4 A = ((const float4*)(gp + 96 + ra * 48))[q];
        float4 Bv = ((const float4*)(gp + 96 + rb * 48))[q];
        w1p[4 * q + 0] = pack2(A.x, Bv.x);
        w1p[4 * q + 1] = pack2(A.y, Bv.y);
        w1p[4 * q + 2] = pack2(A.z, Bv.z);
        w1p[4 * q + 3] = pack2(A.w, Bv.w);
    }
#pragma unroll
    for (int q = 0; q < 12; q++) {
        float4 A = ((const float4*)(gp + 2448 + ra * 48))[q];
        float4 Bv = ((const float4*)(gp + 2448 + rb * 48))[q];
        w2p[4 * q + 0] = pack2(A.x, Bv.x);
        w2p[4 * q + 1] = pack2(A.y, Bv.y);
        w2p[4 * q + 2] = pack2(A.z, Bv.z);
        w2p[4 * q + 3] = pack2(A.w, Bv.w);
    }
    const float w0a = gp[ra],        b0a = gp[48 + ra];
    const float w0b = gp[rb],        b0b = gp[48 + rb];
    const ull   b1pk = pack2(gp[2400 + ra], gp[2400 + rb]);
    const ull   b2pk = pack2(gp[4752 + ra], gp[4752 + rb]);
    const float w3a = gp[4800 + ra];
    const float w3b = two ? gp[4800 + rb] : 0.f;

    float y = 0.f, m = 0.f, v = 0.f;
    float c1 = 1.f, c2 = 1.f;

#pragma unroll 1
    for (int step = 0; step < 20; step++) {
        // ----- layer 0 -----
        {
            float z  = fmaf(w0a, y, b0a);
            float sg = sigf(z);
            float ha = z * sg;
            float da = sg * fmaf(z, 1.f - sg, 1.f) * w0a;
            HD4[ra] = make_float4(ha, ha, da, da);
            if (two) {
                float zb = fmaf(w0b, y, b0b);
                float sb = sigf(zb);
                float hb = zb * sb;
                float db = sb * fmaf(zb, 1.f - sb, 1.f) * w0b;
                HD4[lane + 32] = make_float4(hb, hb, db, db);
            }
        }
        __syncwarp();

        // ----- layer 1: packed value+tangent matvec -----
        ull accz = b1pk, acct = 0ull;
#pragma unroll
        for (int k = 0; k < 48; k++) {
            ulonglong2 q = *(const ulonglong2*)(HD4 + k);  // (h,h),(dh,dh)
            FFMA2(accz, w1p[k], q.x, accz);
            FFMA2(acct, w1p[k], q.y, acct);
        }
        __syncwarp();
        {
            float za, zb, ta, tb;
            unpack2(accz, za, zb);
            unpack2(acct, ta, tb);
            float sg = sigf(za);
            float ha = za * sg;
            float da = sg * fmaf(za, 1.f - sg, 1.f) * ta;
            HD4[ra] = make_float4(ha, ha, da, da);
            if (two) {
                float sb = sigf(zb);
                float hb = zb * sb;
                float db = sb * fmaf(zb, 1.f - sb, 1.f) * tb;
                HD4[lane + 32] = make_float4(hb, hb, db, db);
            }
        }
        __syncwarp();

        // ----- layer 2 + output -----
        accz = b2pk; acct = 0ull;
#pragma unroll
        for (int k = 0; k < 48; k++) {
            ulonglong2 q = *(const ulonglong2*)(HD4 + k);
            FFMA2(accz, w2p[k], q.x, accz);
            FFMA2(acct, w2p[k], q.y, acct);
        }
        float za, zb, ta, tb;
        unpack2(accz, za, zb);
        unpack2(acct, ta, tb);
        float sg = sigf(za);
        float g  = w3a * (sg * fmaf(za, 1.f - sg, 1.f) * ta);
        {
            float sb = sigf(zb);
            float gb = w3b * (sb * fmaf(zb, 1.f - sb, 1.f) * tb);
            if (two) g += gb;
        }
#pragma unroll
        for (int o = 16; o; o >>= 1) g += __shfl_xor_sync(0xffffffffu, g, o);

        // ----- Adam update -----
        c1 *= 0.9f; c2 *= 0.999f;
        m = fmaf(0.9f, m, 0.1f * g);
        v = fmaf(0.999f, v, 0.001f * g * g);
        float mh = m / (1.f - c1);
        float vh = v / (1.f - c2);
        y -= 0.1f * mh / (sqrtf(vh) + 1e-8f);
        __syncwarp();
    }

    if (lane == 0) out[s] = y;
}

// ---------------------------------------------------------------------------
extern "C" void kernel_launch(void* const* d_in, const int* in_sizes, int n_in,
                              void* d_out, int out_size)
{
    const float* x   = (const float*)d_in[0];
    const float* c   = (const float*)d_in[1];
    const float* hw1 = (const float*)d_in[2];
    const float* hb1 = (const float*)d_in[3];
    const float* hw2 = (const float*)d_in[4];
    const float* hb2 = (const float*)d_in[5];
    float* out = (float*)d_out;

    cudaFuncSetAttribute(gemm_kernel, cudaFuncAttributeMaxDynamicSharedMemorySize, GEMM_SMEM);

    dim3 ggrid((P_RAW + BN - 1) / BN, B_SAMP / BM);   // 38 x 64
    gemm_kernel<<<ggrid, GEMM_THREADS, GEMM_SMEM>>>(x, c, hw1, hb1, hw2, hb2);
    adam_kernel<<<B_SAMP / 4, 128>>>(out);
}